// round 11
// baseline (speedup 1.0000x reference)
#include <cuda_runtime.h>
#include <math.h>

// PairPairSupConLoss — algebraic reduction (verified R8, rel_err 6e-8):
//   u = normalize(f_i), w = normalize(f_j)
//   r1 = (s41+s11)/(T*n1), n1^2 = s62+2*s32+1
//   r2 = (s32+s11)/(T*n2), n2^2 = s44+2*s23+1
//   exp_sum[i,j] = (i==j) ? 0 : exp(r1)+3*exp(r2)
//   loss = (1/B) sum_i ( log(sum_j exp_sum) - (sum_j r1)/B )
// With p = u^3 w, q = u^2 w^2:
//   s11=u.w  s41=p.u  s32=p.w  s62=p.p  s23=q.w  s44=q.q
// -> only planes {u,u^2,u^3} (A side) and {w,w^2} (B side) needed.

namespace {
constexpr int Bsz = 512;
constexpr int Dd  = 256;
constexpr int TM  = 64;
constexpr int TN  = 32;
constexpr int KC  = 16;
constexpr int NJT = Bsz / TN;      // 16
constexpr float TINV = 1.0f / 0.07f;
}

// power planes of normalized features, transposed: [plane][k][row]
__device__ __align__(16) float g_pow[3][Dd][Bsz];
__device__ float g_part1[Bsz][NJT];
__device__ float g_partE[Bsz][NJT];

// ---- packed f32x2 helpers (Blackwell FFMA2 path, PTX-only) -----------------
__device__ __forceinline__ unsigned long long pk2(float x, float y) {
    unsigned long long d;
    asm("mov.b64 %0, {%1, %2};" : "=l"(d) : "f"(x), "f"(y));
    return d;
}
__device__ __forceinline__ unsigned long long pkdup(float x) {
    unsigned long long d;
    asm("mov.b64 %0, {%1, %1};" : "=l"(d) : "f"(x));
    return d;
}
__device__ __forceinline__ unsigned long long mul2(unsigned long long a, unsigned long long b) {
    unsigned long long d;
    asm("mul.rn.f32x2 %0, %1, %2;" : "=l"(d) : "l"(a), "l"(b));
    return d;
}
__device__ __forceinline__ void fma2(unsigned long long& d, unsigned long long a, unsigned long long b) {
    asm("fma.rn.f32x2 %0, %1, %2, %0;" : "+l"(d) : "l"(a), "l"(b));
}
__device__ __forceinline__ float2 upk(unsigned long long v) {
    float2 r;
    asm("mov.b64 {%0, %1}, %2;" : "=f"(r.x), "=f"(r.y) : "l"(v));
    return r;
}

// ---------------------------------------------------------------------------
// Kernel 1: row L2-normalize + power planes, smem transpose so the
// transposed global writes are fully coalesced (128B per warp-store).
// grid = 16 blocks x 256 threads; block handles 32 rows.
// ---------------------------------------------------------------------------
__global__ __launch_bounds__(256) void k_norm_pow(const float* __restrict__ f) {
    __shared__ float su[32][260];
    __shared__ float sinv[32];
    const int tid  = threadIdx.x;
    const int lane = tid & 31, warp = tid >> 5;
    const int i0   = blockIdx.x * 32;

    #pragma unroll
    for (int r = 0; r < 4; r++) {
        const int row = warp * 4 + r;
        const float4 x0 = *reinterpret_cast<const float4*>(f + (size_t)(i0 + row) * Dd + lane * 4);
        const float4 x1 = *reinterpret_cast<const float4*>(f + (size_t)(i0 + row) * Dd + 128 + lane * 4);
        *reinterpret_cast<float4*>(&su[row][lane * 4])       = x0;
        *reinterpret_cast<float4*>(&su[row][128 + lane * 4]) = x1;
        float s = x0.x * x0.x + x0.y * x0.y + x0.z * x0.z + x0.w * x0.w
                + x1.x * x1.x + x1.y * x1.y + x1.z * x1.z + x1.w * x1.w;
        #pragma unroll
        for (int o = 16; o > 0; o >>= 1) s += __shfl_xor_sync(0xffffffffu, s, o);
        if (lane == 0) sinv[row] = 1.0f / fmaxf(sqrtf(s), 1e-12f);
    }
    __syncthreads();

    const int i  = tid & 31;          // row within tile -> contiguous across warp
    const int kq = tid >> 5;          // 0..7
    const float inv = sinv[i];
    #pragma unroll
    for (int s = 0; s < 32; s++) {
        const int k = kq * 32 + s;
        const float u  = su[i][k] * inv;
        const float u2 = u * u;
        const float u3 = u2 * u;
        g_pow[0][k][i0 + i] = u;      // coalesced: warp writes 32 consecutive i
        g_pow[1][k][i0 + i] = u2;
        g_pow[2][k][i0 + i] = u3;
    }
}

// ---------------------------------------------------------------------------
// Kernel 2: pairwise tile kernel, packed f32x2 math, cp.async double buffer.
// grid = (8, 16) = 128 blocks, 128 threads, 4x4 microtile (j packed in pairs).
// ---------------------------------------------------------------------------
__global__ __launch_bounds__(128) void k_pair() {
    __shared__ __align__(16) float As[2][3][KC][TM];   // 24 KB
    __shared__ __align__(16) float Bs[2][2][KC][TN];   //  8 KB
    __shared__ float red1[8][TM];
    __shared__ float redE[8][TM];

    const int tid = threadIdx.x;
    const int tx  = tid & 15;
    const int ty  = tid >> 4;
    const int i0  = blockIdx.x * TM;
    const int j0  = blockIdx.y * TN;
    const float* gp = &g_pow[0][0][0];

    // per-thread cp.async descriptors (6 x 16B for A tile, 2 x 16B for B tile)
    const float* aptr[6]; unsigned sa[2][6];
    #pragma unroll
    for (int t = 0; t < 6; t++) {
        const int v = tid + 128 * t;
        const int p = v >> 8, rem = v & 255, kk = rem >> 4, i4 = rem & 15;
        aptr[t]  = gp + ((size_t)(p * Dd + kk) * Bsz + i0 + i4 * 4);
        sa[0][t] = (unsigned)__cvta_generic_to_shared(&As[0][p][kk][i4 * 4]);
        sa[1][t] = (unsigned)__cvta_generic_to_shared(&As[1][p][kk][i4 * 4]);
    }
    const float* bptr[2]; unsigned sb[2][2];
    #pragma unroll
    for (int t = 0; t < 2; t++) {
        const int v = tid + 128 * t;
        const int p = v >> 7, rem = v & 127, kk = rem >> 3, j4 = rem & 7;
        bptr[t]  = gp + ((size_t)(p * Dd + kk) * Bsz + j0 + j4 * 4);
        sb[0][t] = (unsigned)__cvta_generic_to_shared(&Bs[0][p][kk][j4 * 4]);
        sb[1][t] = (unsigned)__cvta_generic_to_shared(&Bs[1][p][kk][j4 * 4]);
    }

    unsigned long long a11[4][2] = {}, a41[4][2] = {}, a32[4][2] = {},
                       a62[4][2] = {}, a23[4][2] = {}, a44[4][2] = {};

    // prologue: chunk 0 -> buffer 0
    #pragma unroll
    for (int t = 0; t < 6; t++)
        asm volatile("cp.async.cg.shared.global [%0], [%1], 16;" :: "r"(sa[0][t]), "l"(aptr[t]) : "memory");
    #pragma unroll
    for (int t = 0; t < 2; t++)
        asm volatile("cp.async.cg.shared.global [%0], [%1], 16;" :: "r"(sb[0][t]), "l"(bptr[t]) : "memory");
    asm volatile("cp.async.commit_group;" ::: "memory");

    for (int c = 0; c < Dd / KC; c++) {
        const int buf = c & 1;
        asm volatile("cp.async.wait_group 0;" ::: "memory");
        __syncthreads();
        if (c + 1 < Dd / KC) {
            const size_t off = (size_t)(c + 1) * KC * Bsz;
            #pragma unroll
            for (int t = 0; t < 6; t++)
                asm volatile("cp.async.cg.shared.global [%0], [%1], 16;" :: "r"(sa[buf ^ 1][t]), "l"(aptr[t] + off) : "memory");
            #pragma unroll
            for (int t = 0; t < 2; t++)
                asm volatile("cp.async.cg.shared.global [%0], [%1], 16;" :: "r"(sb[buf ^ 1][t]), "l"(bptr[t] + off) : "memory");
            asm volatile("cp.async.commit_group;" ::: "memory");
        }

        #pragma unroll
        for (int kk = 0; kk < KC; kk++) {
            const float4 U1 = *reinterpret_cast<const float4*>(&As[buf][0][kk][tx * 4]);
            const float4 U2 = *reinterpret_cast<const float4*>(&As[buf][1][kk][tx * 4]);
            const float4 U3 = *reinterpret_cast<const float4*>(&As[buf][2][kk][tx * 4]);
            const float4 W1 = *reinterpret_cast<const float4*>(&Bs[buf][0][kk][ty * 4]);
            const float4 W2 = *reinterpret_cast<const float4*>(&Bs[buf][1][kk][ty * 4]);
            const unsigned long long w1p[2] = { pk2(W1.x, W1.y), pk2(W1.z, W1.w) };
            const unsigned long long w2p[2] = { pk2(W2.x, W2.y), pk2(W2.z, W2.w) };
            const float u1s[4] = {U1.x, U1.y, U1.z, U1.w};
            const float u2s[4] = {U2.x, U2.y, U2.z, U2.w};
            const float u3s[4] = {U3.x, U3.y, U3.z, U3.w};
            #pragma unroll
            for (int a = 0; a < 4; a++) {
                const unsigned long long up1 = pkdup(u1s[a]);
                const unsigned long long up2 = pkdup(u2s[a]);
                const unsigned long long up3 = pkdup(u3s[a]);
                #pragma unroll
                for (int bp = 0; bp < 2; bp++) {
                    const unsigned long long p2 = mul2(up3, w1p[bp]);   // u^3 w
                    const unsigned long long q2 = mul2(up2, w2p[bp]);   // u^2 w^2
                    fma2(a11[a][bp], up1, w1p[bp]);   // u w
                    fma2(a41[a][bp], p2,  up1);       // u^4 w
                    fma2(a32[a][bp], p2,  w1p[bp]);   // u^3 w^2
                    fma2(a62[a][bp], p2,  p2);        // u^6 w^2
                    fma2(a23[a][bp], q2,  w1p[bp]);   // u^2 w^3
                    fma2(a44[a][bp], q2,  q2);        // u^4 w^4
                }
            }
        }
    }

    // Epilogue: r1, r2, per-row partials for this j-tile.
    float row1[4], rowE[4];
    #pragma unroll
    for (int a = 0; a < 4; a++) {
        const int ig = i0 + tx * 4 + a;
        float s1 = 0.f, sE = 0.f;
        #pragma unroll
        for (int bp = 0; bp < 2; bp++) {
            const float2 v11 = upk(a11[a][bp]);
            const float2 v41 = upk(a41[a][bp]);
            const float2 v32 = upk(a32[a][bp]);
            const float2 v62 = upk(a62[a][bp]);
            const float2 v23 = upk(a23[a][bp]);
            const float2 v44 = upk(a44[a][bp]);
            #pragma unroll
            for (int h = 0; h < 2; h++) {
                const int jg = j0 + ty * 4 + bp * 2 + h;
                const float s11 = h ? v11.y : v11.x;
                const float s41 = h ? v41.y : v41.x;
                const float s32 = h ? v32.y : v32.x;
                const float s62 = h ? v62.y : v62.x;
                const float s23 = h ? v23.y : v23.x;
                const float s44 = h ? v44.y : v44.x;
                const float inv1 = rsqrtf(fmaxf(s62 + 2.f * s32 + 1.f, 1e-24f));
                const float r1 = (s41 + s11) * inv1 * TINV;
                const float inv2 = rsqrtf(fmaxf(s44 + 2.f * s23 + 1.f, 1e-24f));
                const float r2 = (s32 + s11) * inv2 * TINV;
                s1 += r1;
                if (ig != jg) sE += __expf(r1) + 3.f * __expf(r2);
            }
        }
        row1[a] = s1;
        rowE[a] = sE;
    }
    #pragma unroll
    for (int a = 0; a < 4; a++) {
        red1[ty][tx * 4 + a] = row1[a];
        redE[ty][tx * 4 + a] = rowE[a];
    }
    __syncthreads();
    if (tid < TM) {
        float s1 = 0.f, sE = 0.f;
        #pragma unroll
        for (int t = 0; t < 8; t++) { s1 += red1[t][tid]; sE += redE[t][tid]; }
        g_part1[i0 + tid][blockIdx.y] = s1;
        g_partE[i0 + tid][blockIdx.y] = sE;
    }
}

// ---------------------------------------------------------------------------
// Kernel 3: final row reduction + scalar loss. 1 block of B threads.
// ---------------------------------------------------------------------------
__global__ void k_final(float* __restrict__ out) {
    const int i = threadIdx.x;   // 0..511
    float s1 = 0.f, vs = 0.f;
    #pragma unroll
    for (int t = 0; t < NJT; t++) { s1 += g_part1[i][t]; vs += g_partE[i][t]; }
    float term = logf(vs) - s1 * (1.0f / (float)Bsz);

    __shared__ float red[Bsz];
    red[i] = term;
    __syncthreads();
    for (int s = Bsz / 2; s > 0; s >>= 1) {
        if (i < s) red[i] += red[i + s];
        __syncthreads();
    }
    if (i == 0) out[0] = red[0] * (1.0f / (float)Bsz);
}

// ---------------------------------------------------------------------------
extern "C" void kernel_launch(void* const* d_in, const int* in_sizes, int n_in,
                              void* d_out, int out_size) {
    (void)in_sizes; (void)n_in; (void)out_size;
    const float* f = (const float*)d_in[0];

    k_norm_pow<<<Bsz / 32, 256>>>(f);
    dim3 grid(Bsz / TM, Bsz / TN);   // (8, 16) = 128 blocks
    k_pair<<<grid, 128>>>();
    k_final<<<1, Bsz>>>((float*)d_out);
}

// round 12
// speedup vs baseline: 1.0106x; 1.0106x over previous
#include <cuda_runtime.h>
#include <math.h>

// PairPairSupConLoss — algebraic reduction (verified R8, rel_err 6e-8):
//   u = normalize(f_i), w = normalize(f_j)
//   r1 = (s41+s11)/(T*n1), n1^2 = s62+2*s32+1
//   r2 = (s32+s11)/(T*n2), n2^2 = s44+2*s23+1
//   exp_sum[i,j] = (i==j) ? 0 : exp(r1)+3*exp(r2)
//   loss = (1/B) sum_i ( log(sum_j exp_sum) - (sum_j r1)/B )
// With p = u^3 w, q = u^2 w^2:
//   s11=u.w  s41=p.u  s32=p.w  s62=p.p  s23=q.w  s44=q.q
// -> only planes {u,u^2,u^3} (A side) and {w,w^2} (B side) needed.

namespace {
constexpr int Bsz = 512;
constexpr int Dd  = 256;
constexpr int TM  = 64;
constexpr int TN  = 32;
constexpr int KC  = 16;
constexpr int NJT = Bsz / TN;      // 16
constexpr float TINV = 1.0f / 0.07f;
}

// power planes of normalized features, transposed: [plane][k][row]
__device__ __align__(16) float g_pow[3][Dd][Bsz];
__device__ float g_part1[Bsz][NJT];
__device__ float g_partE[Bsz][NJT];

// ---- packed f32x2 helpers (Blackwell FFMA2 path, PTX-only) -----------------
__device__ __forceinline__ unsigned long long pk2(float x, float y) {
    unsigned long long d;
    asm("mov.b64 %0, {%1, %2};" : "=l"(d) : "f"(x), "f"(y));
    return d;
}
__device__ __forceinline__ unsigned long long pkdup(float x) {
    unsigned long long d;
    asm("mov.b64 %0, {%1, %1};" : "=l"(d) : "f"(x));
    return d;
}
__device__ __forceinline__ unsigned long long mul2(unsigned long long a, unsigned long long b) {
    unsigned long long d;
    asm("mul.rn.f32x2 %0, %1, %2;" : "=l"(d) : "l"(a), "l"(b));
    return d;
}
__device__ __forceinline__ void fma2(unsigned long long& d, unsigned long long a, unsigned long long b) {
    asm("fma.rn.f32x2 %0, %1, %2, %0;" : "+l"(d) : "l"(a), "l"(b));
}
__device__ __forceinline__ float2 upk(unsigned long long v) {
    float2 r;
    asm("mov.b64 {%0, %1}, %2;" : "=f"(r.x), "=f"(r.y) : "l"(v));
    return r;
}

// ---------------------------------------------------------------------------
// Kernel 1: row L2-normalize + power planes, smem transpose so the
// transposed global writes are fully coalesced (128B per warp-store).
// grid = 16 blocks x 256 threads; block handles 32 rows.
// ---------------------------------------------------------------------------
__global__ __launch_bounds__(256) void k_norm_pow(const float* __restrict__ f) {
    __shared__ float su[32][260];
    __shared__ float sinv[32];
    const int tid  = threadIdx.x;
    const int lane = tid & 31, warp = tid >> 5;
    const int i0   = blockIdx.x * 32;

    #pragma unroll
    for (int r = 0; r < 4; r++) {
        const int row = warp * 4 + r;
        const float4 x0 = *reinterpret_cast<const float4*>(f + (size_t)(i0 + row) * Dd + lane * 4);
        const float4 x1 = *reinterpret_cast<const float4*>(f + (size_t)(i0 + row) * Dd + 128 + lane * 4);
        *reinterpret_cast<float4*>(&su[row][lane * 4])       = x0;
        *reinterpret_cast<float4*>(&su[row][128 + lane * 4]) = x1;
        float s = x0.x * x0.x + x0.y * x0.y + x0.z * x0.z + x0.w * x0.w
                + x1.x * x1.x + x1.y * x1.y + x1.z * x1.z + x1.w * x1.w;
        #pragma unroll
        for (int o = 16; o > 0; o >>= 1) s += __shfl_xor_sync(0xffffffffu, s, o);
        if (lane == 0) sinv[row] = 1.0f / fmaxf(sqrtf(s), 1e-12f);
    }
    __syncthreads();

    const int i  = tid & 31;          // row within tile -> contiguous across warp
    const int kq = tid >> 5;          // 0..7
    const float inv = sinv[i];
    #pragma unroll
    for (int s = 0; s < 32; s++) {
        const int k = kq * 32 + s;
        const float u  = su[i][k] * inv;
        const float u2 = u * u;
        const float u3 = u2 * u;
        g_pow[0][k][i0 + i] = u;      // coalesced: warp writes 32 consecutive i
        g_pow[1][k][i0 + i] = u2;
        g_pow[2][k][i0 + i] = u3;
    }
}

// ---------------------------------------------------------------------------
// Kernel 2: pairwise tile kernel, packed f32x2 math, cp.async double buffer.
// grid = (8, 16) = 128 blocks, 128 threads, 4x4 microtile (j packed in pairs).
// ---------------------------------------------------------------------------
__global__ __launch_bounds__(128) void k_pair() {
    __shared__ __align__(16) float As[2][3][KC][TM];   // 24 KB
    __shared__ __align__(16) float Bs[2][2][KC][TN];   //  8 KB
    __shared__ float red1[8][TM];
    __shared__ float redE[8][TM];

    const int tid = threadIdx.x;
    const int tx  = tid & 15;
    const int ty  = tid >> 4;
    const int i0  = blockIdx.x * TM;
    const int j0  = blockIdx.y * TN;
    const float* gp = &g_pow[0][0][0];

    // per-thread cp.async descriptors (6 x 16B for A tile, 2 x 16B for B tile)
    const float* aptr[6]; unsigned sa[2][6];
    #pragma unroll
    for (int t = 0; t < 6; t++) {
        const int v = tid + 128 * t;
        const int p = v >> 8, rem = v & 255, kk = rem >> 4, i4 = rem & 15;
        aptr[t]  = gp + ((size_t)(p * Dd + kk) * Bsz + i0 + i4 * 4);
        sa[0][t] = (unsigned)__cvta_generic_to_shared(&As[0][p][kk][i4 * 4]);
        sa[1][t] = (unsigned)__cvta_generic_to_shared(&As[1][p][kk][i4 * 4]);
    }
    const float* bptr[2]; unsigned sb[2][2];
    #pragma unroll
    for (int t = 0; t < 2; t++) {
        const int v = tid + 128 * t;
        const int p = v >> 7, rem = v & 127, kk = rem >> 3, j4 = rem & 7;
        bptr[t]  = gp + ((size_t)(p * Dd + kk) * Bsz + j0 + j4 * 4);
        sb[0][t] = (unsigned)__cvta_generic_to_shared(&Bs[0][p][kk][j4 * 4]);
        sb[1][t] = (unsigned)__cvta_generic_to_shared(&Bs[1][p][kk][j4 * 4]);
    }

    unsigned long long a11[4][2] = {}, a41[4][2] = {}, a32[4][2] = {},
                       a62[4][2] = {}, a23[4][2] = {}, a44[4][2] = {};

    // prologue: chunk 0 -> buffer 0
    #pragma unroll
    for (int t = 0; t < 6; t++)
        asm volatile("cp.async.cg.shared.global [%0], [%1], 16;" :: "r"(sa[0][t]), "l"(aptr[t]) : "memory");
    #pragma unroll
    for (int t = 0; t < 2; t++)
        asm volatile("cp.async.cg.shared.global [%0], [%1], 16;" :: "r"(sb[0][t]), "l"(bptr[t]) : "memory");
    asm volatile("cp.async.commit_group;" ::: "memory");

    for (int c = 0; c < Dd / KC; c++) {
        const int buf = c & 1;
        asm volatile("cp.async.wait_group 0;" ::: "memory");
        __syncthreads();
        if (c + 1 < Dd / KC) {
            const size_t off = (size_t)(c + 1) * KC * Bsz;
            #pragma unroll
            for (int t = 0; t < 6; t++)
                asm volatile("cp.async.cg.shared.global [%0], [%1], 16;" :: "r"(sa[buf ^ 1][t]), "l"(aptr[t] + off) : "memory");
            #pragma unroll
            for (int t = 0; t < 2; t++)
                asm volatile("cp.async.cg.shared.global [%0], [%1], 16;" :: "r"(sb[buf ^ 1][t]), "l"(bptr[t] + off) : "memory");
            asm volatile("cp.async.commit_group;" ::: "memory");
        }

        #pragma unroll
        for (int kk = 0; kk < KC; kk++) {
            const float4 U1 = *reinterpret_cast<const float4*>(&As[buf][0][kk][tx * 4]);
            const float4 U2 = *reinterpret_cast<const float4*>(&As[buf][1][kk][tx * 4]);
            const float4 U3 = *reinterpret_cast<const float4*>(&As[buf][2][kk][tx * 4]);
            const float4 W1 = *reinterpret_cast<const float4*>(&Bs[buf][0][kk][ty * 4]);
            const float4 W2 = *reinterpret_cast<const float4*>(&Bs[buf][1][kk][ty * 4]);
            const unsigned long long w1p[2] = { pk2(W1.x, W1.y), pk2(W1.z, W1.w) };
            const unsigned long long w2p[2] = { pk2(W2.x, W2.y), pk2(W2.z, W2.w) };
            const float u1s[4] = {U1.x, U1.y, U1.z, U1.w};
            const float u2s[4] = {U2.x, U2.y, U2.z, U2.w};
            const float u3s[4] = {U3.x, U3.y, U3.z, U3.w};
            #pragma unroll
            for (int a = 0; a < 4; a++) {
                const unsigned long long up1 = pkdup(u1s[a]);
                const unsigned long long up2 = pkdup(u2s[a]);
                const unsigned long long up3 = pkdup(u3s[a]);
                #pragma unroll
                for (int bp = 0; bp < 2; bp++) {
                    const unsigned long long p2 = mul2(up3, w1p[bp]);   // u^3 w
                    const unsigned long long q2 = mul2(up2, w2p[bp]);   // u^2 w^2
                    fma2(a11[a][bp], up1, w1p[bp]);   // u w
                    fma2(a41[a][bp], p2,  up1);       // u^4 w
                    fma2(a32[a][bp], p2,  w1p[bp]);   // u^3 w^2
                    fma2(a62[a][bp], p2,  p2);        // u^6 w^2
                    fma2(a23[a][bp], q2,  w1p[bp]);   // u^2 w^3
                    fma2(a44[a][bp], q2,  q2);        // u^4 w^4
                }
            }
        }
    }

    // Epilogue: r1, r2, per-row partials for this j-tile.
    float row1[4], rowE[4];
    #pragma unroll
    for (int a = 0; a < 4; a++) {
        const int ig = i0 + tx * 4 + a;
        float s1 = 0.f, sE = 0.f;
        #pragma unroll
        for (int bp = 0; bp < 2; bp++) {
            const float2 v11 = upk(a11[a][bp]);
            const float2 v41 = upk(a41[a][bp]);
            const float2 v32 = upk(a32[a][bp]);
            const float2 v62 = upk(a62[a][bp]);
            const float2 v23 = upk(a23[a][bp]);
            const float2 v44 = upk(a44[a][bp]);
            #pragma unroll
            for (int h = 0; h < 2; h++) {
                const int jg = j0 + ty * 4 + bp * 2 + h;
                const float s11 = h ? v11.y : v11.x;
                const float s41 = h ? v41.y : v41.x;
                const float s32 = h ? v32.y : v32.x;
                const float s62 = h ? v62.y : v62.x;
                const float s23 = h ? v23.y : v23.x;
                const float s44 = h ? v44.y : v44.x;
                const float inv1 = rsqrtf(fmaxf(s62 + 2.f * s32 + 1.f, 1e-24f));
                const float r1 = (s41 + s11) * inv1 * TINV;
                const float inv2 = rsqrtf(fmaxf(s44 + 2.f * s23 + 1.f, 1e-24f));
                const float r2 = (s32 + s11) * inv2 * TINV;
                s1 += r1;
                if (ig != jg) sE += __expf(r1) + 3.f * __expf(r2);
            }
        }
        row1[a] = s1;
        rowE[a] = sE;
    }
    #pragma unroll
    for (int a = 0; a < 4; a++) {
        red1[ty][tx * 4 + a] = row1[a];
        redE[ty][tx * 4 + a] = rowE[a];
    }
    __syncthreads();
    if (tid < TM) {
        float s1 = 0.f, sE = 0.f;
        #pragma unroll
        for (int t = 0; t < 8; t++) { s1 += red1[t][tid]; sE += redE[t][tid]; }
        g_part1[i0 + tid][blockIdx.y] = s1;
        g_partE[i0 + tid][blockIdx.y] = sE;
    }
}

// ---------------------------------------------------------------------------
// Kernel 3: final row reduction + scalar loss. 1 block of B threads.
// ---------------------------------------------------------------------------
__global__ void k_final(float* __restrict__ out) {
    const int i = threadIdx.x;   // 0..511
    float s1 = 0.f, vs = 0.f;
    #pragma unroll
    for (int t = 0; t < NJT; t++) { s1 += g_part1[i][t]; vs += g_partE[i][t]; }
    float term = logf(vs) - s1 * (1.0f / (float)Bsz);

    __shared__ float red[Bsz];
    red[i] = term;
    __syncthreads();
    for (int s = Bsz / 2; s > 0; s >>= 1) {
        if (i < s) red[i] += red[i + s];
        __syncthreads();
    }
    if (i == 0) out[0] = red[0] * (1.0f / (float)Bsz);
}

// ---------------------------------------------------------------------------
extern "C" void kernel_launch(void* const* d_in, const int* in_sizes, int n_in,
                              void* d_out, int out_size) {
    (void)in_sizes; (void)n_in; (void)out_size;
    const float* f = (const float*)d_in[0];

    k_norm_pow<<<Bsz / 32, 256>>>(f);
    dim3 grid(Bsz / TM, Bsz / TN);   // (8, 16) = 128 blocks
    k_pair<<<grid, 128>>>();
    k_final<<<1, Bsz>>>((float*)d_out);
}